// round 16
// baseline (speedup 1.0000x reference)
#include <cuda_runtime.h>
#include <math.h>

// Problem constants (fixed by setup_inputs)
#define BS   16
#define NQ   550
#define NC   91
#define NT   48
#define GN   11
#define GQ   (NQ / GN)       // 50
#define NTOT (BS * NT)       // 768
#define NMATCH (GN * NT)     // 528

#define LSA_N 48   // rows (targets) of transposed problem
#define LSA_M 50   // cols (queries)
#define NPROB (BS * GN)      // 176 LSA problems
#define NQROWS (BS * NQ)     // 8800 cost-matrix rows
#define COSTB  (NQROWS / 2)  // 4400 cost blocks, 2 rows each
#define FULLMASK 0xffffffffu
#define ARR_PASSES 6

#define SCALE39 549755813888.0      // 2^39 fixed-point scale
#define BIAS51  (1LL << 51)
#define PADV    (1LL << 50)         // sentinel: scaled "2048", >> any real cost
#define USEDV   ((1LL << 51) - 1)   // used-column candidate sentinel
#define LL_INF  0x7FFFFFFFFFFFFFFFLL

// ---------------------------------------------------------------------------
// focal class cost (identical f32 expression)
// ---------------------------------------------------------------------------
__device__ __forceinline__ float focal_eval(float x)
{
    float p = 1.0f / (1.0f + expf(-x));
    float omp = 1.0f - p;
    float pos = 0.25f * omp * omp * (-logf(p + 1e-8f));
    float neg = 0.75f * p * p * (-logf(omp + 1e-8f));
    return pos - neg;
}

// ---------------------------------------------------------------------------
// box/giou part of the cost (identical float expression/order everywhere)
// ---------------------------------------------------------------------------
__device__ __forceinline__ float cost_box(
    float cx, float cy, float l, float r, float tp, float bo,
    float ax0, float ay0, float ax1, float ay1, float a1,
    const float* __restrict__ tb, float cost_class)
{
    float tcx = tb[0], tcy = tb[1], tl = tb[2], tr = tb[3], ttp = tb[4], tbo = tb[5];

    float c3d   = fabsf(cx - tcx) + fabsf(cy - tcy);
    float cbbox = fabsf(l - tl) + fabsf(r - tr) + fabsf(tp - ttp) + fabsf(bo - tbo);

    float bx0 = tcx - tl, by0 = tcy - ttp, bx1 = tcx + tr, by1 = tcy + tbo;
    float a2 = (bx1 - bx0) * (by1 - by0);
    float iw = fmaxf(fminf(ax1, bx1) - fmaxf(ax0, bx0), 0.0f);
    float ih = fmaxf(fminf(ay1, by1) - fmaxf(ay0, by0), 0.0f);
    float inter = iw * ih;
    float uni = a1 + a2 - inter;
    float iou = inter / uni;
    float ew = fmaxf(fmaxf(ax1, bx1) - fminf(ax0, bx0), 0.0f);
    float eh = fmaxf(fmaxf(ay1, by1) - fminf(ay0, by0), 0.0f);
    float ae = ew * eh;
    float giou = iou - (ae - uni) / ae;

    return 5.0f * cbbox + 10.0f * c3d + 2.0f * cost_class + 2.0f * (-giou);
}

// full cost for LSA tile path (computes focal inline; same expression)
__device__ __forceinline__ float cost_eval(
    float cx, float cy, float l, float r, float tp, float bo,
    int q, int t,
    const float* __restrict__ logits,
    const int* __restrict__ labels, const float* __restrict__ tboxes)
{
    float ax0 = cx - l, ay0 = cy - tp, ax1 = cx + r, ay1 = cy + bo;
    float a1 = (ax1 - ax0) * (ay1 - ay0);
    float cc = focal_eval(logits[q * NC + labels[t]]);
    return cost_box(cx, cy, l, r, tp, bo, ax0, ay0, ax1, ay1, a1,
                    tboxes + t * 6, cc);
}

// warp-min over 58-bit keys packed as ((val+BIAS51)<<6)|col
__device__ __forceinline__ unsigned long long warp_min58(unsigned long long key)
{
    unsigned hi = (unsigned)(key >> 32);
    unsigned hmin = __reduce_min_sync(FULLMASK, hi);
    unsigned lo = (hi == hmin) ? (unsigned)key : 0xFFFFFFFFu;
    unsigned lmin = __reduce_min_sync(FULLMASK, lo);
    return ((unsigned long long)hmin << 32) | lmin;
}

// ---------------------------------------------------------------------------
// Fused kernel: blocks [0, NPROB) run JV-LSA; blocks [NPROB, NPROB+COSTB)
// each fill TWO rows of C with per-row smem focal tables (class dedup).
// ---------------------------------------------------------------------------
__global__ void __launch_bounds__(256)
fused_kernel(const float* __restrict__ logits,
             const float* __restrict__ pboxes,
             const int*   __restrict__ labels,
             const float* __restrict__ tboxes,
             float* __restrict__ C,
             float* __restrict__ pi_out,
             float* __restrict__ ti_out,
             int do_lsa)
{
    int tid = threadIdx.x;

    // ---------------- cost-matrix cohort: two q rows per block ----------------
    if (blockIdx.x >= NPROB) {
        int q0 = (blockIdx.x - NPROB) * 2;
        __shared__ float foc[2][NC];
        if (tid < NC)                        foc[0][tid]       = focal_eval(logits[q0 * NC + tid]);
        else if (tid >= 128 && tid < 128 + NC) foc[1][tid - 128] = focal_eval(logits[(q0 + 1) * NC + tid - 128]);
        __syncthreads();

        int half = tid >> 7;                 // 0 or 1
        int lt   = tid & 127;
        int q = q0 + half;
        const float* qb = pboxes + q * 6;
        float cx = qb[0], cy = qb[1], l = qb[2], r = qb[3], tp = qb[4], bo = qb[5];
        float ax0 = cx - l, ay0 = cy - tp, ax1 = cx + r, ay1 = cy + bo;
        float a1 = (ax1 - ax0) * (ay1 - ay0);

        #pragma unroll
        for (int k = 0; k < NTOT / 128; k++) {
            int t = lt + k * 128;
            float cc = foc[half][labels[t]];
            C[q * NTOT + t] = cost_box(cx, cy, l, r, tp, bo,
                                       ax0, ay0, ax1, ay1, a1,
                                       tboxes + t * 6, cc);
        }
        return;
    }

    // ---------------- LSA cohort ----------------
    if (!do_lsa) return;
    int prob = blockIdx.x;
    int b = prob / GN;
    int g = prob - b * GN;

    __shared__ long long costp[LSA_N][64];   // fixed-point costs; cols 50..63 = PADV
    __shared__ long long u_s[LSA_N + 1];
    __shared__ int p_s[66];
    __shared__ int way_s[66];
    __shared__ int rowmin_j[LSA_N + 1];
    __shared__ int claim[LSA_M + 1];
    __shared__ int row_done[LSA_N + 1];

    // compute + quantize the 48x50 diagonal tile
    for (int idx = tid; idx < LSA_N * LSA_M; idx += 256) {
        int jj = idx / LSA_N;
        int i  = idx - jj * LSA_N;
        int q = b * NQ + g * GQ + jj;
        const float* qb = pboxes + q * 6;
        float c = cost_eval(qb[0], qb[1], qb[2], qb[3], qb[4], qb[5],
                            q, b * NT + i, logits, labels, tboxes);
        costp[i][jj] = __double2ll_rn((double)c * SCALE39);
    }
    // sentinel padding columns 50..63
    for (int idx = tid; idx < LSA_N * 14; idx += 256) {
        int i = idx / 14, c = 50 + (idx - (idx / 14) * 14);
        costp[i][c] = PADV;
    }
    if (tid >= 64 && tid < 64 + 66) { p_s[tid - 64] = 0; way_s[tid - 64] = 0; }
    if (tid >= 130 && tid < 130 + LSA_M + 1) claim[tid - 130] = 1 << 30;
    if (tid == 63) u_s[0] = 0LL;
    __syncthreads();

    // warm start: u[i] = row min (exact), greedy claim of argmin columns
    if (tid < LSA_N) {
        int i = tid;
        long long bestk = LL_INF;
        #pragma unroll 1
        for (int s = 0; s < LSA_M; s++) {
            int jj = i + s; if (jj >= LSA_M) jj -= LSA_M;   // staggered, conflict-free
            long long kk = ((costp[i][jj] + BIAS51) << 6) | jj;  // tie -> smaller j
            if (kk < bestk) bestk = kk;
        }
        int jarg = (int)(bestk & 63);
        u_s[i + 1] = (bestk >> 6) - BIAS51;
        rowmin_j[i + 1] = jarg + 1;
        row_done[i + 1] = 0;
        atomicMin(&claim[jarg + 1], i + 1);    // smallest row wins = row-order greedy
    }
    __syncthreads();
    if (tid < LSA_N) {
        int i = tid + 1;
        int j = rowmin_j[i];
        if (claim[j] == i) { p_s[j] = i; row_done[i] = 1; }  // tight edge
    }
    __syncthreads();
    if (tid >= 32) return;

    int lane = tid;
    const int colA = 2 * lane + 1;          // 1-based owned columns (pads >= 51)
    const int colB = 2 * lane + 2;
    long long v0 = 0, v1 = 0;

    // ------- augmenting row reduction over free rows (pad lanes never win) ---
    for (int pass = 0; pass < ARR_PASSES; pass++) {
        for (int i = 1; i <= LSA_N; i++) {
            if (row_done[i]) continue;

            longlong2 cf = *(const longlong2*)&costp[i - 1][2 * lane];
            unsigned long long kA =
                ((unsigned long long)(cf.x - v0 + BIAS51) << 6) | (unsigned)colA;
            unsigned long long kB =
                ((unsigned long long)(cf.y - v1 + BIAS51) << 6) | (unsigned)colB;
            unsigned long long kloc = (kA <= kB) ? kA : kB;
            unsigned long long k1 = warp_min58(kloc);
            int j1 = (int)(k1 & 63u);
            long long val1 = (long long)(k1 >> 6) - BIAS51;

            unsigned long long kA2 = (colA == j1) ? ~0ULL : kA;
            unsigned long long kB2 = (colB == j1) ? ~0ULL : kB;
            unsigned long long kloc2 = (kA2 <= kB2) ? kA2 : kB2;
            unsigned long long k2 = warp_min58(kloc2);
            int j2 = (int)(k2 & 63u);
            long long val2 = (long long)(k2 >> 6) - BIAS51;

            int jsel = j1;
            if (val1 == val2 && p_s[j1] != 0) jsel = j2;   // tie: try second column
            int kdisp = p_s[jsel];
            __syncwarp();
            if (lane == 0) {
                p_s[jsel] = i;
                u_s[i] = val2;
                row_done[i] = 1;
                if (kdisp) row_done[kdisp] = 0;   // displaced row becomes free
            }
            if (val1 < val2) {                     // lower v[j1] so it stays tight
                int owner = (j1 - 1) >> 1;
                if (lane == owner) {
                    if ((j1 - 1) & 1) v1 -= (val2 - val1); else v0 -= (val2 - val1);
                }
            }
            __syncwarp();
        }
    }

    int pr0 = p_s[colA];
    int pr1 = p_s[colB];
    __syncwarp();

    // ------- frame-invariant successive shortest-path phases -------
    // M[j] = min_t (cur_t[j] + S_{t-1}); exact integer telescoping of the
    // reference recurrence. Duals frame-invariant + feasible => used columns
    // can never be improved by relax (cur >= S_{t-1} >= M at selection), so
    // unconditional relax is safe and `way` is final at selection time.
    for (int i = 1; i <= LSA_N; i++) {
        if (row_done[i]) continue;

        long long M0 = PADV, M1 = PADV;
        int way0 = 0, way1 = 0;             // register way for my 2 columns
        unsigned used2 = 0;
        long long S = 0;                    // S_{t-1}
        long long ui0 = u_s[i];             // phase-start u of scan row
        int i0 = i;
        int j0 = 0;

        while (true) {
            // relax columns from row i0 (exact integer, fully branchless)
            longlong2 cf = *(const longlong2*)&costp[i0 - 1][2 * lane];
            long long base = S - ui0;
            long long cur0 = cf.x - v0 + base;
            long long cur1 = cf.y - v1 + base;
            bool b0 = cur0 < M0;  M0 = b0 ? cur0 : M0;  way0 = b0 ? j0 : way0;
            bool b1 = cur1 < M1;  M1 = b1 ? cur1 : M1;  way1 = b1 ? j0 : way1;

            // lane-local best among not-used (tie -> colA, the smaller index)
            long long ca  = (used2 & 1u) ? USEDV : M0;
            long long cb2 = (used2 & 2u) ? USEDV : M1;
            bool pickA = (ca <= cb2);
            long long mb = pickA ? ca : cb2;
            unsigned bj = pickA ? (unsigned)colA : (unsigned)colB;
            int psel    = pickA ? pr0 : pr1;

            // 52-bit key (unconditional): hi32 | (lo20, col6, p[col]6)
            unsigned long long key = (unsigned long long)(mb + BIAS51);
            unsigned hi = (unsigned)(key >> 20);
            unsigned packv = (((unsigned)key & 0xFFFFFu) << 12) | (bj << 6)
                             | (unsigned)psel;

            unsigned hmin = __reduce_min_sync(FULLMASK, hi);
            unsigned pk = (hi == hmin) ? packv : 0xFFFFFFFFu;
            unsigned pkm = __reduce_min_sync(FULLMASK, pk);
            unsigned jmin = (pkm >> 6) & 63u;
            int pval = (int)(pkm & 63u);
            S = (long long)((((unsigned long long)hmin << 20) | (pkm >> 12))) - BIAS51;

            j0 = (int)jmin;
            if (pval == 0) break;             // reached a free column
            unsigned mine = (unsigned)(lane == (int)((jmin - 1) >> 1));
            used2 |= mine << ((jmin - 1) & 1u);
            i0 = pval;
            ui0 = u_s[pval];                  // phase-start value (u_s untouched in-phase)
        }

        // phase-end dual reconciliation: d_j = S_end - M[j] for used columns
        long long S_end = S;
        if (used2 & 1u) { long long d = S_end - M0; v0 -= d; u_s[pr0] += d; }
        if (used2 & 2u) { long long d = S_end - M1; v1 -= d; u_s[pr1] += d; }
        if (lane == 0) u_s[i] += S_end;
        // publish register ways for the augmentation walk
        way_s[colA] = way0;
        way_s[colB] = way1;
        __syncwarp();

        // augment alternating path
        if (lane == 0) {
            int jc = j0;
            while (jc) {
                int jn = way_s[jc];
                p_s[jc] = (jn == 0) ? i : p_s[jn];
                jc = jn;
            }
        }
        __syncwarp();
        pr0 = p_s[colA];
        pr1 = p_s[colB];
    }

    // Emit matches: queries ascending (48 of 50 columns assigned)
    if (lane == 0) {
        int base = b * NMATCH + g * NT;
        int k = 0;
        for (int j = 1; j <= LSA_M; j++) {
            int pj = p_s[j];
            if (pj) {
                pi_out[base + k] = (float)(g * GQ + j - 1);
                ti_out[base + k] = (float)(pj - 1);
                k++;
            }
        }
    }
}

// ---------------------------------------------------------------------------
extern "C" void kernel_launch(void* const* d_in, const int* in_sizes, int n_in,
                              void* d_out, int out_size)
{
    const float* logits = (const float*)d_in[0];  // (16,550,91)
    const float* pboxes = (const float*)d_in[1];  // (16,550,6)
    const int*   labels = (const int*)  d_in[2];  // (16,48)
    const float* tboxes = (const float*)d_in[3];  // (16,48,6)

    float* C  = (float*)d_out;
    const int C_ELEMS = BS * NQ * NTOT;          // 6,758,400
    float* pi = C + C_ELEMS;
    float* ti = pi + BS * NMATCH;

    int do_lsa = (out_size >= C_ELEMS + 2 * BS * NMATCH) ? 1 : 0;
    fused_kernel<<<NPROB + COSTB, 256>>>(logits, pboxes, labels, tboxes,
                                         C, pi, ti, do_lsa);
}

// round 17
// speedup vs baseline: 1.0637x; 1.0637x over previous
#include <cuda_runtime.h>
#include <math.h>

// Problem constants (fixed by setup_inputs)
#define BS   16
#define NQ   550
#define NC   91
#define NT   48
#define GN   11
#define GQ   (NQ / GN)       // 50
#define NTOT (BS * NT)       // 768
#define NMATCH (GN * NT)     // 528

#define LSA_N 48   // rows (targets) of transposed problem
#define LSA_M 50   // cols (queries)
#define NPROB (BS * GN)      // 176 LSA problems
#define NQROWS (BS * NQ)     // 8800 cost-matrix rows (one block each)
#define FULLMASK 0xffffffffu
#define ARR_PASSES 4

#define SCALE39 549755813888.0      // 2^39 fixed-point scale
#define BIAS51  (1LL << 51)
#define PADV    (1LL << 50)         // sentinel: scaled "2048", >> any real cost
#define USEDV   ((1LL << 51) - 1)   // used-column candidate sentinel
#define LL_INF  0x7FFFFFFFFFFFFFFFLL

// ---------------------------------------------------------------------------
// focal class cost (identical f32 expression)
// ---------------------------------------------------------------------------
__device__ __forceinline__ float focal_eval(float x)
{
    float p = 1.0f / (1.0f + expf(-x));
    float omp = 1.0f - p;
    float pos = 0.25f * omp * omp * (-logf(p + 1e-8f));
    float neg = 0.75f * p * p * (-logf(omp + 1e-8f));
    return pos - neg;
}

// ---------------------------------------------------------------------------
// box/giou part of the cost (identical float expression/order everywhere)
// ---------------------------------------------------------------------------
__device__ __forceinline__ float cost_box(
    float cx, float cy, float l, float r, float tp, float bo,
    float ax0, float ay0, float ax1, float ay1, float a1,
    const float* __restrict__ tb, float cost_class)
{
    float tcx = tb[0], tcy = tb[1], tl = tb[2], tr = tb[3], ttp = tb[4], tbo = tb[5];

    float c3d   = fabsf(cx - tcx) + fabsf(cy - tcy);
    float cbbox = fabsf(l - tl) + fabsf(r - tr) + fabsf(tp - ttp) + fabsf(bo - tbo);

    float bx0 = tcx - tl, by0 = tcy - ttp, bx1 = tcx + tr, by1 = tcy + tbo;
    float a2 = (bx1 - bx0) * (by1 - by0);
    float iw = fmaxf(fminf(ax1, bx1) - fmaxf(ax0, bx0), 0.0f);
    float ih = fmaxf(fminf(ay1, by1) - fmaxf(ay0, by0), 0.0f);
    float inter = iw * ih;
    float uni = a1 + a2 - inter;
    float iou = inter / uni;
    float ew = fmaxf(fmaxf(ax1, bx1) - fminf(ax0, bx0), 0.0f);
    float eh = fmaxf(fmaxf(ay1, by1) - fminf(ay0, by0), 0.0f);
    float ae = ew * eh;
    float giou = iou - (ae - uni) / ae;

    return 5.0f * cbbox + 10.0f * c3d + 2.0f * cost_class + 2.0f * (-giou);
}

// full cost for LSA tile path (computes focal inline; same expression)
__device__ __forceinline__ float cost_eval(
    float cx, float cy, float l, float r, float tp, float bo,
    int q, int t,
    const float* __restrict__ logits,
    const int* __restrict__ labels, const float* __restrict__ tboxes)
{
    float ax0 = cx - l, ay0 = cy - tp, ax1 = cx + r, ay1 = cy + bo;
    float a1 = (ax1 - ax0) * (ay1 - ay0);
    float cc = focal_eval(logits[q * NC + labels[t]]);
    return cost_box(cx, cy, l, r, tp, bo, ax0, ay0, ax1, ay1, a1,
                    tboxes + t * 6, cc);
}

// warp-min over 58-bit keys packed as ((val+BIAS51)<<6)|col
__device__ __forceinline__ unsigned long long warp_min58(unsigned long long key)
{
    unsigned hi = (unsigned)(key >> 32);
    unsigned hmin = __reduce_min_sync(FULLMASK, hi);
    unsigned lo = (hi == hmin) ? (unsigned)key : 0xFFFFFFFFu;
    unsigned lmin = __reduce_min_sync(FULLMASK, lo);
    return ((unsigned long long)hmin << 32) | lmin;
}

// ---------------------------------------------------------------------------
// Fused kernel: blocks [0, NPROB) run JV-LSA; blocks [NPROB, NPROB+NQROWS)
// each fill ONE row of C with a per-block smem focal table (class dedup).
// ---------------------------------------------------------------------------
__global__ void __launch_bounds__(256)
fused_kernel(const float* __restrict__ logits,
             const float* __restrict__ pboxes,
             const int*   __restrict__ labels,
             const float* __restrict__ tboxes,
             float* __restrict__ C,
             float* __restrict__ pi_out,
             float* __restrict__ ti_out,
             int do_lsa)
{
    int tid = threadIdx.x;

    // ---------------- cost-matrix cohort: one q row per block ----------------
    if (blockIdx.x >= NPROB) {
        int q = blockIdx.x - NPROB;          // 0..NQROWS-1
        __shared__ float foc[NC];
        if (tid < NC) foc[tid] = focal_eval(logits[q * NC + tid]);
        __syncthreads();

        const float* qb = pboxes + q * 6;
        float cx = qb[0], cy = qb[1], l = qb[2], r = qb[3], tp = qb[4], bo = qb[5];
        float ax0 = cx - l, ay0 = cy - tp, ax1 = cx + r, ay1 = cy + bo;
        float a1 = (ax1 - ax0) * (ay1 - ay0);

        #pragma unroll
        for (int k = 0; k < NTOT / 256; k++) {
            int t = tid + k * 256;
            float cc = foc[labels[t]];
            C[q * NTOT + t] = cost_box(cx, cy, l, r, tp, bo,
                                       ax0, ay0, ax1, ay1, a1,
                                       tboxes + t * 6, cc);
        }
        return;
    }

    // ---------------- LSA cohort ----------------
    if (!do_lsa) return;
    int prob = blockIdx.x;
    int b = prob / GN;
    int g = prob - b * GN;

    __shared__ long long costp[LSA_N][64];   // fixed-point costs; cols 50..63 = PADV
    __shared__ long long u_s[LSA_N + 1];
    __shared__ int p_s[66];
    __shared__ int way_s[66];
    __shared__ int rowmin_j[LSA_N + 1];
    __shared__ int claim[LSA_M + 1];
    __shared__ int row_done[LSA_N + 1];

    // compute + quantize the 48x50 diagonal tile
    for (int idx = tid; idx < LSA_N * LSA_M; idx += 256) {
        int jj = idx / LSA_N;
        int i  = idx - jj * LSA_N;
        int q = b * NQ + g * GQ + jj;
        const float* qb = pboxes + q * 6;
        float c = cost_eval(qb[0], qb[1], qb[2], qb[3], qb[4], qb[5],
                            q, b * NT + i, logits, labels, tboxes);
        costp[i][jj] = __double2ll_rn((double)c * SCALE39);
    }
    // sentinel padding columns 50..63
    for (int idx = tid; idx < LSA_N * 14; idx += 256) {
        int i = idx / 14, c = 50 + (idx - (idx / 14) * 14);
        costp[i][c] = PADV;
    }
    if (tid >= 64 && tid < 64 + 66) { p_s[tid - 64] = 0; way_s[tid - 64] = 0; }
    if (tid >= 130 && tid < 130 + LSA_M + 1) claim[tid - 130] = 1 << 30;
    if (tid == 63) u_s[0] = 0LL;
    __syncthreads();

    // warm start: u[i] = row min (exact), greedy claim of argmin columns
    if (tid < LSA_N) {
        int i = tid;
        long long bestk = LL_INF;
        #pragma unroll 1
        for (int s = 0; s < LSA_M; s++) {
            int jj = i + s; if (jj >= LSA_M) jj -= LSA_M;   // staggered, conflict-free
            long long kk = ((costp[i][jj] + BIAS51) << 6) | jj;  // tie -> smaller j
            if (kk < bestk) bestk = kk;
        }
        int jarg = (int)(bestk & 63);
        u_s[i + 1] = (bestk >> 6) - BIAS51;
        rowmin_j[i + 1] = jarg + 1;
        row_done[i + 1] = 0;
        atomicMin(&claim[jarg + 1], i + 1);    // smallest row wins = row-order greedy
    }
    __syncthreads();
    if (tid < LSA_N) {
        int i = tid + 1;
        int j = rowmin_j[i];
        if (claim[j] == i) { p_s[j] = i; row_done[i] = 1; }  // tight edge
    }
    __syncthreads();
    if (tid >= 32) return;

    int lane = tid;
    const int colA = 2 * lane + 1;          // 1-based owned columns (pads >= 51)
    const int colB = 2 * lane + 2;
    long long v0 = 0, v1 = 0;

    // ------- augmenting row reduction over free rows (pad lanes never win) ---
    for (int pass = 0; pass < ARR_PASSES; pass++) {
        for (int i = 1; i <= LSA_N; i++) {
            if (row_done[i]) continue;

            longlong2 cf = *(const longlong2*)&costp[i - 1][2 * lane];
            unsigned long long kA =
                ((unsigned long long)(cf.x - v0 + BIAS51) << 6) | (unsigned)colA;
            unsigned long long kB =
                ((unsigned long long)(cf.y - v1 + BIAS51) << 6) | (unsigned)colB;
            unsigned long long kloc = (kA <= kB) ? kA : kB;
            unsigned long long k1 = warp_min58(kloc);
            int j1 = (int)(k1 & 63u);
            long long val1 = (long long)(k1 >> 6) - BIAS51;

            unsigned long long kA2 = (colA == j1) ? ~0ULL : kA;
            unsigned long long kB2 = (colB == j1) ? ~0ULL : kB;
            unsigned long long kloc2 = (kA2 <= kB2) ? kA2 : kB2;
            unsigned long long k2 = warp_min58(kloc2);
            int j2 = (int)(k2 & 63u);
            long long val2 = (long long)(k2 >> 6) - BIAS51;

            int jsel = j1;
            if (val1 == val2 && p_s[j1] != 0) jsel = j2;   // tie: try second column
            int kdisp = p_s[jsel];
            __syncwarp();
            if (lane == 0) {
                p_s[jsel] = i;
                u_s[i] = val2;
                row_done[i] = 1;
                if (kdisp) row_done[kdisp] = 0;   // displaced row becomes free
            }
            if (val1 < val2) {                     // lower v[j1] so it stays tight
                int owner = (j1 - 1) >> 1;
                if (lane == owner) {
                    if ((j1 - 1) & 1) v1 -= (val2 - val1); else v0 -= (val2 - val1);
                }
            }
            __syncwarp();
        }
    }

    int pr0 = p_s[colA];
    int pr1 = p_s[colB];
    __syncwarp();

    // ------- frame-invariant successive shortest-path phases -------
    // M[j] = min_t (cur_t[j] + S_{t-1}); exact integer telescoping of the
    // reference recurrence. Duals frame-invariant + feasible => used columns
    // can never be improved by relax (cur >= S_{t-1} >= M at selection), so
    // unconditional relax is safe and `way` is final at selection time ->
    // way lives in registers, dumped to smem only at phase end.
    for (int i = 1; i <= LSA_N; i++) {
        if (row_done[i]) continue;

        long long M0 = PADV, M1 = PADV;
        int way0 = 0, way1 = 0;             // register way for my 2 columns
        unsigned used2 = 0;
        long long S = 0;                    // S_{t-1}
        long long ui0 = u_s[i];             // phase-start u of scan row
        int i0 = i;
        int j0 = 0;

        while (true) {
            // relax columns from row i0 (exact integer, fully branchless)
            longlong2 cf = *(const longlong2*)&costp[i0 - 1][2 * lane];
            long long base = S - ui0;
            long long cur0 = cf.x - v0 + base;
            long long cur1 = cf.y - v1 + base;
            bool b0 = cur0 < M0;  M0 = b0 ? cur0 : M0;  way0 = b0 ? j0 : way0;
            bool b1 = cur1 < M1;  M1 = b1 ? cur1 : M1;  way1 = b1 ? j0 : way1;

            // lane-local best among not-used (tie -> colA, the smaller index)
            long long ca  = (used2 & 1u) ? USEDV : M0;
            long long cb2 = (used2 & 2u) ? USEDV : M1;
            bool pickA = (ca <= cb2);
            long long mb = pickA ? ca : cb2;
            unsigned bj = pickA ? (unsigned)colA : (unsigned)colB;
            int psel    = pickA ? pr0 : pr1;

            // 52-bit key (unconditional): hi32 | (lo20, col6, p[col]6)
            unsigned long long key = (unsigned long long)(mb + BIAS51);
            unsigned hi = (unsigned)(key >> 20);
            unsigned packv = (((unsigned)key & 0xFFFFFu) << 12) | (bj << 6)
                             | (unsigned)psel;

            unsigned hmin = __reduce_min_sync(FULLMASK, hi);
            unsigned pk = (hi == hmin) ? packv : 0xFFFFFFFFu;
            unsigned pkm = __reduce_min_sync(FULLMASK, pk);
            unsigned jmin = (pkm >> 6) & 63u;
            int pval = (int)(pkm & 63u);
            S = (long long)((((unsigned long long)hmin << 20) | (pkm >> 12))) - BIAS51;

            j0 = (int)jmin;
            if (pval == 0) break;             // reached a free column
            unsigned mine = (unsigned)(lane == (int)((jmin - 1) >> 1));
            used2 |= mine << ((jmin - 1) & 1u);
            i0 = pval;
            ui0 = u_s[pval];                  // phase-start value (u_s untouched in-phase)
        }

        // phase-end dual reconciliation: d_j = S_end - M[j] for used columns
        long long S_end = S;
        if (used2 & 1u) { long long d = S_end - M0; v0 -= d; u_s[pr0] += d; }
        if (used2 & 2u) { long long d = S_end - M1; v1 -= d; u_s[pr1] += d; }
        if (lane == 0) u_s[i] += S_end;
        // publish register ways for the augmentation walk
        way_s[colA] = way0;
        way_s[colB] = way1;
        __syncwarp();

        // augment alternating path
        if (lane == 0) {
            int jc = j0;
            while (jc) {
                int jn = way_s[jc];
                p_s[jc] = (jn == 0) ? i : p_s[jn];
                jc = jn;
            }
        }
        __syncwarp();
        pr0 = p_s[colA];
        pr1 = p_s[colB];
    }

    // Emit matches: queries ascending (48 of 50 columns assigned)
    if (lane == 0) {
        int base = b * NMATCH + g * NT;
        int k = 0;
        for (int j = 1; j <= LSA_M; j++) {
            int pj = p_s[j];
            if (pj) {
                pi_out[base + k] = (float)(g * GQ + j - 1);
                ti_out[base + k] = (float)(pj - 1);
                k++;
            }
        }
    }
}

// ---------------------------------------------------------------------------
extern "C" void kernel_launch(void* const* d_in, const int* in_sizes, int n_in,
                              void* d_out, int out_size)
{
    const float* logits = (const float*)d_in[0];  // (16,550,91)
    const float* pboxes = (const float*)d_in[1];  // (16,550,6)
    const int*   labels = (const int*)  d_in[2];  // (16,48)
    const float* tboxes = (const float*)d_in[3];  // (16,48,6)

    float* C  = (float*)d_out;
    const int C_ELEMS = BS * NQ * NTOT;          // 6,758,400
    float* pi = C + C_ELEMS;
    float* ti = pi + BS * NMATCH;

    int do_lsa = (out_size >= C_ELEMS + 2 * BS * NMATCH) ? 1 : 0;
    fused_kernel<<<NPROB + NQROWS, 256>>>(logits, pboxes, labels, tboxes,
                                          C, pi, ti, do_lsa);
}